// round 6
// baseline (speedup 1.0000x reference)
#include <cuda_runtime.h>

// NEAT feed-forward DAG evaluator — R6: 2 CTAs/SM for cross-CTA latency hiding.
// x[4096,512] f32, W[1536,2048] f32 strictly lower-tri, b[1536], out[4096,256].
//
// Per CTA: BR=8 batch rows (256 threads, ~101.6KB smem -> 2 CTAs resident/SM).
// One CTA's serial triangle / barriers overlap the other CTA's GEMM.
// Per chunk of CC=64 nodes:
//   phase 1: panel GEMM, warp=k-split (8), per-thread 4r x 4c x 8k,
//            W staged as k-pair float2 (wS2[kpair][node]), double-buffered,
//            one barrier per 64-k block.
//   epilogue: split-K partials overlay the DEAD wS2 buffer; diagonal block
//            staged (j-pair layout) into the free wS2 buffer; reduce -> zACC.
//   phase 2: 64-node triangle, one warp per batch row.

#define NTHREADS 256
#define BR 8
#define CC 64
#define NIN 512
#define NEVAL 1536
#define NN 2048
#define NOUT 256
#define NCHUNK (NEVAL / CC)      // 24
#define SO 2052                  // outS row stride (floats); pad so row pairs
                                 // 4 apart land on different bank halves
#define WS2R 66                  // wS2 row stride in float2 units (16B-aligned rows)
#define WS2SZ (32 * WS2R)        // one buffer: 32 kpair rows (float2 units)
#define ZACCR 66

#define SMEM_FLOATS (BR*SO + 2*WS2SZ*2 + BR*ZACCR)
#define SMEM_BYTES (SMEM_FLOATS * 4)

__global__ void __launch_bounds__(NTHREADS, 2)
neat_ff_kernel(const float* __restrict__ x,
               const float* __restrict__ W,
               const float* __restrict__ bias,
               float* __restrict__ out)
{
    extern __shared__ float smem[];
    float*  outS = smem;                       // [BR][SO]
    float2* wS2  = (float2*)(outS + BR * SO);  // 2 x [32 kpair][WS2R]
    float*  zACC = (float*)(wS2 + 2 * WS2SZ);  // [BR][ZACCR] reduced z

    const int tid  = threadIdx.x;
    const int row0 = blockIdx.x * BR;

    // ---- load x tile (float4, coalesced) ----
    for (int i = tid; i < BR * (NIN / 4); i += NTHREADS) {
        int r = i >> 7, q = i & 127;
        *(float4*)&outS[r * SO + 4 * q] = *(const float4*)&x[(row0 + r) * NIN + 4 * q];
    }

    // GEMM mapping: warp = k-split sp (8k each); lane -> 4 rows x 4 cols
    const int sp   = tid >> 5;                 // 0..7 (uniform per warp)
    const int lane = tid & 31;
    const int cq   = lane & 15;  const int c0 = 4 * cq;
    const int rg   = lane >> 4;  const int r0 = 4 * rg;

    // staging: thread moves one node's 4 k-quads (node ssc, quads sq0+4p)
    const int ssc = tid >> 2;                  // 0..63
    const int sq0 = tid & 3;                   // quad base

    // prefetch first W block (chunk 0, kb 0)
    float4 v0 = *(const float4*)&W[ssc * NN + 4 * (sq0 + 0)];
    float4 v1 = *(const float4*)&W[ssc * NN + 4 * (sq0 + 4)];
    float4 v2 = *(const float4*)&W[ssc * NN + 4 * (sq0 + 8)];
    float4 v3 = *(const float4*)&W[ssc * NN + 4 * (sq0 + 12)];

    int buf = 0;

    for (int ch = 0; ch < NCHUNK; ch++) {
        const int i0 = ch * CC;
        const int g0 = NIN + i0;

        float acc[4][4];
        #pragma unroll
        for (int r = 0; r < 4; r++)
            #pragma unroll
            for (int c = 0; c < 4; c++) acc[r][c] = 0.0f;

        // ---- phase 1: panel GEMM, one barrier per 64-k block ----
        for (int kb = 0; kb < g0; kb += CC) {
            {   // commit prefetched block -> wS2[buf], k-pair layout
                float2* b = wS2 + buf * WS2SZ;
                b[(2*(sq0+ 0)  )*WS2R + ssc] = make_float2(v0.x, v0.y);
                b[(2*(sq0+ 0)+1)*WS2R + ssc] = make_float2(v0.z, v0.w);
                b[(2*(sq0+ 4)  )*WS2R + ssc] = make_float2(v1.x, v1.y);
                b[(2*(sq0+ 4)+1)*WS2R + ssc] = make_float2(v1.z, v1.w);
                b[(2*(sq0+ 8)  )*WS2R + ssc] = make_float2(v2.x, v2.y);
                b[(2*(sq0+ 8)+1)*WS2R + ssc] = make_float2(v2.z, v2.w);
                b[(2*(sq0+12)  )*WS2R + ssc] = make_float2(v3.x, v3.y);
                b[(2*(sq0+12)+1)*WS2R + ssc] = make_float2(v3.z, v3.w);
            }
            __syncthreads();
            {   // prefetch next block (diag block when nkb == g0)
                int nkb = kb + CC;
                const float* wr = &W[(i0 + ssc) * NN + nkb];
                v0 = *(const float4*)&wr[4 * (sq0 + 0)];
                v1 = *(const float4*)&wr[4 * (sq0 + 4)];
                v2 = *(const float4*)&wr[4 * (sq0 + 8)];
                v3 = *(const float4*)&wr[4 * (sq0 + 12)];
            }
            // micro-kernel: 2 quads of 4 k
            const float2* wb = wS2 + buf * WS2SZ;
            #pragma unroll
            for (int q = 0; q < 2; q++) {
                const int kk = 8 * sp + 4 * q;
                const int kp = 4 * sp + 2 * q;
                float4 w0 = *(const float4*)(wb +  kp      * WS2R + c0);
                float4 w1 = *(const float4*)(wb +  kp      * WS2R + c0 + 2);
                float4 w2 = *(const float4*)(wb + (kp + 1) * WS2R + c0);
                float4 w3 = *(const float4*)(wb + (kp + 1) * WS2R + c0 + 2);
                #pragma unroll
                for (int r = 0; r < 4; r++) {
                    float4 a = *(const float4*)&outS[(r0 + r) * SO + kb + kk];
                    acc[r][0] = fmaf(a.x, w0.x, acc[r][0]);
                    acc[r][1] = fmaf(a.x, w0.z, acc[r][1]);
                    acc[r][2] = fmaf(a.x, w1.x, acc[r][2]);
                    acc[r][3] = fmaf(a.x, w1.z, acc[r][3]);
                    acc[r][0] = fmaf(a.y, w0.y, acc[r][0]);
                    acc[r][1] = fmaf(a.y, w0.w, acc[r][1]);
                    acc[r][2] = fmaf(a.y, w1.y, acc[r][2]);
                    acc[r][3] = fmaf(a.y, w1.w, acc[r][3]);
                    acc[r][0] = fmaf(a.z, w2.x, acc[r][0]);
                    acc[r][1] = fmaf(a.z, w2.z, acc[r][1]);
                    acc[r][2] = fmaf(a.z, w3.x, acc[r][2]);
                    acc[r][3] = fmaf(a.z, w3.z, acc[r][3]);
                    acc[r][0] = fmaf(a.w, w2.y, acc[r][0]);
                    acc[r][1] = fmaf(a.w, w2.w, acc[r][1]);
                    acc[r][2] = fmaf(a.w, w3.y, acc[r][2]);
                    acc[r][3] = fmaf(a.w, w3.w, acc[r][3]);
                }
            }
            buf ^= 1;
        }
        // after loop: buf == free buffer (last block used buf^1)
        const int bufFree = buf, bufLast = buf ^ 1;

        __syncthreads();   // all compute of last block done before overlays

        // split-K partials -> overlay region of the DEAD buffer (bufLast)
        float* zSb = (float*)(wS2 + bufLast * WS2SZ);
        #pragma unroll
        for (int r = 0; r < 4; r++)
            *(float4*)&zSb[(sp * BR + r0 + r) * 64 + c0] =
                make_float4(acc[r][0], acc[r][1], acc[r][2], acc[r][3]);
        {   // diag block (in v) -> wS2[bufFree], j-pair layout
            float2* b = wS2 + bufFree * WS2SZ;
            b[(2*(sq0+ 0)  )*WS2R + ssc] = make_float2(v0.x, v0.y);
            b[(2*(sq0+ 0)+1)*WS2R + ssc] = make_float2(v0.z, v0.w);
            b[(2*(sq0+ 4)  )*WS2R + ssc] = make_float2(v1.x, v1.y);
            b[(2*(sq0+ 4)+1)*WS2R + ssc] = make_float2(v1.z, v1.w);
            b[(2*(sq0+ 8)  )*WS2R + ssc] = make_float2(v2.x, v2.y);
            b[(2*(sq0+ 8)+1)*WS2R + ssc] = make_float2(v2.z, v2.w);
            b[(2*(sq0+12)  )*WS2R + ssc] = make_float2(v3.x, v3.y);
            b[(2*(sq0+12)+1)*WS2R + ssc] = make_float2(v3.z, v3.w);
        }
        // prefetch first block of next chunk (overlaps reduce + triangle)
        if (ch + 1 < NCHUNK) {
            const float* wr = &W[(i0 + CC + ssc) * NN];
            v0 = *(const float4*)&wr[4 * (sq0 + 0)];
            v1 = *(const float4*)&wr[4 * (sq0 + 4)];
            v2 = *(const float4*)&wr[4 * (sq0 + 8)];
            v3 = *(const float4*)&wr[4 * (sq0 + 12)];
        }
        __syncthreads();   // zSb + diag visible

        // reduce 8 split-K partials -> zACC
        #pragma unroll
        for (int t = 0; t < 2; t++) {
            int idx = tid + t * NTHREADS;
            int k = idx & 63, r = idx >> 6;
            float s = zSb[r * 64 + k];
            #pragma unroll
            for (int s8 = 1; s8 < 8; s8++)
                s += zSb[(s8 * BR + r) * 64 + k];
            zACC[r * ZACCR + k] = s;
        }
        __syncthreads();   // zACC visible; bufLast free for next chunk commits

        // ---- phase 2: triangle, one warp per batch row (8 warps busy) ----
        {
            const int r  = sp;                 // warp -> batch row
            const int k0 = lane, k1 = lane + 32;
            float a0t = __ldg(&bias[i0 + k0]) + zACC[r * ZACCR + k0];
            float a1t = __ldg(&bias[i0 + k1]) + zACC[r * ZACCR + k1];
            float o0 = 0.f, o1 = 0.f;
            const float2* wd = wS2 + bufFree * WS2SZ;
            #pragma unroll 4
            for (int jp = 0; jp < 32; jp++) {
                float2 wp0 = wd[jp * WS2R + k0];   // W[k0][2jp], W[k0][2jp+1]
                float2 wp1 = wd[jp * WS2R + k1];
                #pragma unroll
                for (int h = 0; h < 2; h++) {
                    int j = 2 * jp + h;
                    float w0 = h ? wp0.y : wp0.x;
                    float w1 = h ? wp1.y : wp1.x;
                    float zj = __shfl_sync(0xffffffffu, (j < 32) ? a0t : a1t, j & 31);
                    float t5 = fminf(fmaxf(5.0f * zj, -60.0f), 60.0f);
                    float o  = __fdividef(1.0f, 1.0f + __expf(-t5));
                    if (j == k0) o0 = o;
                    if (j == k1) o1 = o;
                    if (k0 > j) a0t = fmaf(w0, o, a0t);
                    if (k1 > j) a1t = fmaf(w1, o, a1t);
                }
            }
            outS[r * SO + g0 + k0] = o0;
            outS[r * SO + g0 + k1] = o1;
        }
        // next commit targets bufLast; block-iter barrier orders it vs triangle
        buf = bufLast;
    }

    __syncthreads();
    // ---- write output: last NOUT columns ----
    for (int i = tid; i < BR * (NOUT / 4); i += NTHREADS) {
        int r = i >> 6, q = i & 63;
        *(float4*)&out[(row0 + r) * NOUT + 4 * q] =
            *(const float4*)&outS[r * SO + (NN - NOUT) + 4 * q];
    }
}

extern "C" void kernel_launch(void* const* d_in, const int* in_sizes, int n_in,
                              void* d_out, int out_size) {
    const float* x    = (const float*)d_in[0];
    const float* W    = (const float*)d_in[1];
    const float* bias = (const float*)d_in[2];
    float* out        = (float*)d_out;
    (void)in_sizes; (void)n_in; (void)out_size;

    cudaFuncSetAttribute(neat_ff_kernel,
                         cudaFuncAttributeMaxDynamicSharedMemorySize,
                         SMEM_BYTES);
    neat_ff_kernel<<<4096 / BR, NTHREADS, SMEM_BYTES>>>(x, W, bias, out);
}